// round 1
// baseline (speedup 1.0000x reference)
#include <cuda_runtime.h>
#include <math.h>

// ---------------- problem constants ----------------
#define BSZ   8
#define SEQ   4096
#define DMODEL 512
#define DI    1024      // d_inner
#define DS    16        // d_state
#define DR    32        // dt_rank
#define DFF   2048
#define NTOK  (BSZ*SEQ) // 32768
#define NCH   32        // scan chunks
#define CS    128       // chunk size (NCH*CS == SEQ)
#define LN_EPS 1e-5f

// ---------------- scratch (device globals; no cudaMalloc allowed) ----------------
__device__ float g_xz [(size_t)NTOK*2*DI];   // in-proj output (xi | z)
__device__ float g_xc [(size_t)NTOK*DI];     // conv+silu output
__device__ float g_dbc[(size_t)NTOK*(DR+2*DS)]; // x-proj output (dt_r | B | C)
__device__ float g_dt [(size_t)NTOK*DI];     // softplus(dt)
__device__ float g_yg [(size_t)NTOK*DI];     // gated scan output
__device__ float g_mf [(size_t)NTOK*DMODEL]; // forward mamba out
__device__ float g_mb [(size_t)NTOK*DMODEL]; // backward mamba out (already un-flipped)
__device__ float g_h  [(size_t)NTOK*DMODEL]; // merged hidden
__device__ float g_ff1[(size_t)NTOK*DFF];
__device__ float g_ff2[(size_t)NTOK*DMODEL];
__device__ float g_hend[(size_t)BSZ*NCH*DS*DI];
__device__ float g_P   [(size_t)BSZ*NCH*DS*DI];
__device__ float g_hin [(size_t)BSZ*NCH*DS*DI];

// ---------------- math helpers ----------------
__device__ __forceinline__ float sigmoidf(float x){ return 1.f/(1.f+__expf(-x)); }
__device__ __forceinline__ float geluf(float x){
    float x3 = x*x*x;
    return 0.5f*x*(1.f + tanhf(0.7978845608028654f*(x + 0.044715f*x3)));
}
__device__ __forceinline__ float softplusf(float x){
    return fmaxf(x,0.f) + log1pf(__expf(-fabsf(x)));
}
__device__ __forceinline__ float warpSum(float v){
    #pragma unroll
    for(int o=16;o;o>>=1) v += __shfl_xor_sync(0xffffffffu, v, o);
    return v;
}

// ---------------- generic SGEMM: C[M,N] = act(A[M,K(lda)] @ B[N,K]^T + bias[N]) ----------------
// ACT: 0=none, 1=gelu, 2=softplus
template<int BM,int BN,int BK,int TM,int TN,int ACT>
__global__ void sgemm_tn(const float* __restrict__ A, int lda,
                         const float* __restrict__ B,
                         const float* __restrict__ bias,
                         float* __restrict__ C,
                         int M, int N, int K)
{
    __shared__ float As[BK][BM];
    __shared__ float Bs[BK][BN];
    constexpr int THREADS = (BM/TM)*(BN/TN);
    const int tid = threadIdx.x;
    const int m0 = blockIdx.y*BM, n0 = blockIdx.x*BN;
    const int tx = tid % (BN/TN);
    const int ty = tid / (BN/TN);

    float acc[TM][TN];
    #pragma unroll
    for(int i=0;i<TM;i++)
        #pragma unroll
        for(int j=0;j<TN;j++) acc[i][j]=0.f;

    constexpr int A_F4 = BM*BK/4;
    constexpr int B_F4 = BN*BK/4;

    for (int k0 = 0; k0 < K; k0 += BK) {
        #pragma unroll
        for (int f = tid; f < A_F4; f += THREADS) {
            int row = f / (BK/4);
            int kc  = f % (BK/4);
            float4 v = *reinterpret_cast<const float4*>(&A[(size_t)(m0+row)*lda + k0 + kc*4]);
            As[kc*4+0][row]=v.x; As[kc*4+1][row]=v.y; As[kc*4+2][row]=v.z; As[kc*4+3][row]=v.w;
        }
        #pragma unroll
        for (int f = tid; f < B_F4; f += THREADS) {
            int row = f / (BK/4);
            int kc  = f % (BK/4);
            float4 v = *reinterpret_cast<const float4*>(&B[(size_t)(n0+row)*K + k0 + kc*4]);
            Bs[kc*4+0][row]=v.x; Bs[kc*4+1][row]=v.y; Bs[kc*4+2][row]=v.z; Bs[kc*4+3][row]=v.w;
        }
        __syncthreads();
        #pragma unroll
        for (int k=0;k<BK;k++){
            float rm[TM], rn[TN];
            #pragma unroll
            for(int i=0;i<TM;i++) rm[i]=As[k][ty*TM+i];
            #pragma unroll
            for(int j=0;j<TN;j++) rn[j]=Bs[k][tx*TN+j];
            #pragma unroll
            for(int i=0;i<TM;i++)
                #pragma unroll
                for(int j=0;j<TN;j++)
                    acc[i][j] = fmaf(rm[i], rn[j], acc[i][j]);
        }
        __syncthreads();
    }

    #pragma unroll
    for(int i=0;i<TM;i++){
        int m = m0 + ty*TM + i;
        #pragma unroll
        for(int j=0;j<TN;j++){
            int n = n0 + tx*TN + j;
            float v = acc[i][j];
            if (bias) v += bias[n];
            if (ACT==1) v = geluf(v);
            else if (ACT==2) v = softplusf(v);
            C[(size_t)m*N + n] = v;
        }
    }
}

// ---------------- depthwise causal/anticausal conv (k=4) + bias + silu ----------------
// reads xi = first DI columns of g_xz rows (row stride 2*DI)
__global__ void conv_silu_kernel(const float* __restrict__ xz,
                                 const float* __restrict__ w,
                                 const float* __restrict__ cb,
                                 float* __restrict__ xc, int dir)
{
    int idx = blockIdx.x*blockDim.x + threadIdx.x;
    if (idx >= NTOK*DI) return;
    int d = idx % DI;
    int t = (idx / DI) % SEQ;
    int b =  idx / (DI*SEQ);
    const float* base = xz + ((size_t)b*SEQ)*(2*DI) + d;
    float acc = cb[d];
    #pragma unroll
    for (int j=0;j<4;j++){
        int tt = (dir==0) ? (t-3+j) : (t+3-j);
        if (tt>=0 && tt<SEQ) acc = fmaf(w[d*4+j], base[(size_t)tt*(2*DI)], acc);
    }
    xc[idx] = acc * sigmoidf(acc);
}

// ---------------- chunked selective scan ----------------
// pass1: per (b,d,chunk): local scan from h=0; store end-state and decay product
__global__ void scan_pass1(const float* __restrict__ dt,
                           const float* __restrict__ xc,
                           const float* __restrict__ dbc,
                           const float* __restrict__ A_log,
                           float* __restrict__ hend, float* __restrict__ Pout,
                           int dir)
{
    const int d = blockIdx.x*blockDim.x + threadIdx.x;
    const int c = blockIdx.y, b = blockIdx.z;
    __shared__ float sB[CS][DS];
    for (int i = threadIdx.x; i < CS*DS; i += blockDim.x) {
        int sl = i / DS, q = i % DS;
        int p  = dir ? (SEQ-1 - (c*CS+sl)) : (c*CS+sl);
        sB[sl][q] = dbc[((size_t)b*SEQ + p)*(DR+2*DS) + DR + q];
    }
    __syncthreads();

    float A[DS];
    #pragma unroll
    for (int n=0;n<DS;n++) A[n] = -__expf(A_log[d*DS + n]);

    float h[DS], P[DS];
    #pragma unroll
    for (int n=0;n<DS;n++){ h[n]=0.f; P[n]=1.f; }

    for (int s=0;s<CS;s++){
        int p = dir ? (SEQ-1 - (c*CS+s)) : (c*CS+s);
        size_t off = ((size_t)b*SEQ + p)*DI + d;
        float dtv = dt[off];
        float xv  = xc[off];
        float dtx = dtv*xv;
        #pragma unroll
        for (int n=0;n<DS;n++){
            float dA = __expf(dtv*A[n]);
            h[n] = fmaf(dA, h[n], dtx*sB[s][n]);
            P[n] *= dA;
        }
    }
    size_t base = (((size_t)b*NCH + c)*DS)*DI + d;
    #pragma unroll
    for (int n=0;n<DS;n++){ hend[base + (size_t)n*DI] = h[n]; Pout[base + (size_t)n*DI] = P[n]; }
}

// pass2: sequential combine over chunks -> incoming state per chunk
__global__ void scan_pass2(const float* __restrict__ hend,
                           const float* __restrict__ P,
                           float* __restrict__ hin)
{
    int idx = blockIdx.x*blockDim.x + threadIdx.x; // over BSZ*DS*DI
    if (idx >= BSZ*DS*DI) return;
    int d = idx % DI;
    int n = (idx / DI) % DS;
    int b =  idx / (DI*DS);
    float h = 0.f;
    for (int c=0;c<NCH;c++){
        size_t off = (((size_t)b*NCH + c)*DS + n)*DI + d;
        hin[off] = h;
        h = fmaf(P[off], h, hend[off]);
    }
}

// pass3: replay with incoming state, produce y, fuse +x*D and *silu(z)
__global__ void scan_pass3(const float* __restrict__ dt,
                           const float* __restrict__ xc,
                           const float* __restrict__ dbc,
                           const float* __restrict__ A_log,
                           const float* __restrict__ Dp,
                           const float* __restrict__ xz,
                           const float* __restrict__ hin,
                           float* __restrict__ yg,
                           int dir)
{
    const int d = blockIdx.x*blockDim.x + threadIdx.x;
    const int c = blockIdx.y, b = blockIdx.z;
    __shared__ float sB[CS][DS];
    __shared__ float sC[CS][DS];
    for (int i = threadIdx.x; i < CS*2*DS; i += blockDim.x) {
        int sl = i / (2*DS), q = i % (2*DS);
        int p  = dir ? (SEQ-1 - (c*CS+sl)) : (c*CS+sl);
        float v = dbc[((size_t)b*SEQ + p)*(DR+2*DS) + DR + q];
        if (q < DS) sB[sl][q] = v; else sC[sl][q-DS] = v;
    }
    __syncthreads();

    float A[DS];
    #pragma unroll
    for (int n=0;n<DS;n++) A[n] = -__expf(A_log[d*DS + n]);
    float h[DS];
    {
        size_t base = (((size_t)b*NCH + c)*DS)*DI + d;
        #pragma unroll
        for (int n=0;n<DS;n++) h[n] = hin[base + (size_t)n*DI];
    }
    const float Dval = Dp[d];

    for (int s=0;s<CS;s++){
        int p = dir ? (SEQ-1 - (c*CS+s)) : (c*CS+s);
        size_t off = ((size_t)b*SEQ + p)*DI + d;
        float dtv = dt[off];
        float xv  = xc[off];
        float dtx = dtv*xv;
        float y = 0.f;
        #pragma unroll
        for (int n=0;n<DS;n++){
            float dA = __expf(dtv*A[n]);
            h[n] = fmaf(dA, h[n], dtx*sB[s][n]);
            y = fmaf(h[n], sC[s][n], y);
        }
        float zz = xz[((size_t)b*SEQ + p)*(2*DI) + DI + d];
        yg[off] = (y + xv*Dval) * (zz * sigmoidf(zz));
    }
}

// ---------------- h = 0.5*(LN(x+mf; f) + LN(x+mb; b)) ----------------
__global__ void ln_combine_kernel(const float* __restrict__ x,
                                  const float* __restrict__ mf,
                                  const float* __restrict__ mb,
                                  const float* __restrict__ gf, const float* __restrict__ bf,
                                  const float* __restrict__ gb, const float* __restrict__ bb,
                                  float* __restrict__ hout)
{
    const int row = blockIdx.x;
    const size_t base = (size_t)row*DMODEL;
    const int t4 = threadIdx.x;        // 128 threads, float4 each
    float4 x4  = *reinterpret_cast<const float4*>(&x [base + t4*4]);
    float4 f4  = *reinterpret_cast<const float4*>(&mf[base + t4*4]);
    float4 b4  = *reinterpret_cast<const float4*>(&mb[base + t4*4]);
    float a[4] = {x4.x+f4.x, x4.y+f4.y, x4.z+f4.z, x4.w+f4.w};
    float c[4] = {x4.x+b4.x, x4.y+b4.y, x4.z+b4.z, x4.w+b4.w};
    float sa=0, sa2=0, sc=0, sc2=0;
    #pragma unroll
    for (int i=0;i<4;i++){ sa+=a[i]; sa2+=a[i]*a[i]; sc+=c[i]; sc2+=c[i]*c[i]; }

    __shared__ float red[4][4];
    float vals[4] = {sa, sa2, sc, sc2};
    int warp = threadIdx.x>>5, lane = threadIdx.x&31;
    #pragma unroll
    for (int q=0;q<4;q++){
        float w = warpSum(vals[q]);
        if (lane==0) red[q][warp] = w;
    }
    __syncthreads();
    float tot[4];
    #pragma unroll
    for (int q=0;q<4;q++) tot[q] = red[q][0]+red[q][1]+red[q][2]+red[q][3];

    float ma = tot[0]*(1.f/DMODEL);
    float va = tot[1]*(1.f/DMODEL) - ma*ma;
    float ra = rsqrtf(va + LN_EPS);
    float mc = tot[2]*(1.f/DMODEL);
    float vc = tot[3]*(1.f/DMODEL) - mc*mc;
    float rc = rsqrtf(vc + LN_EPS);

    float4 out;
    float* po = &out.x;
    #pragma unroll
    for (int i=0;i<4;i++){
        int col = t4*4+i;
        float la = (a[i]-ma)*ra*gf[col] + bf[col];
        float lc = (c[i]-mc)*rc*gb[col] + bb[col];
        po[i] = 0.5f*(la + lc);
    }
    *reinterpret_cast<float4*>(&hout[base + t4*4]) = out;
}

// ---------------- out = LN(h + ff2; ln_ff) ----------------
__global__ void ln_final_kernel(const float* __restrict__ h,
                                const float* __restrict__ ff2,
                                const float* __restrict__ g, const float* __restrict__ bta,
                                float* __restrict__ out)
{
    const int row = blockIdx.x;
    const size_t base = (size_t)row*DMODEL;
    const int t4 = threadIdx.x;
    float4 h4 = *reinterpret_cast<const float4*>(&h  [base + t4*4]);
    float4 f4 = *reinterpret_cast<const float4*>(&ff2[base + t4*4]);
    float a[4] = {h4.x+f4.x, h4.y+f4.y, h4.z+f4.z, h4.w+f4.w};
    float sa=0, sa2=0;
    #pragma unroll
    for (int i=0;i<4;i++){ sa+=a[i]; sa2+=a[i]*a[i]; }

    __shared__ float red[2][4];
    int warp = threadIdx.x>>5, lane = threadIdx.x&31;
    float w0 = warpSum(sa), w1 = warpSum(sa2);
    if (lane==0){ red[0][warp]=w0; red[1][warp]=w1; }
    __syncthreads();
    float ts  = red[0][0]+red[0][1]+red[0][2]+red[0][3];
    float ts2 = red[1][0]+red[1][1]+red[1][2]+red[1][3];
    float mu = ts*(1.f/DMODEL);
    float var = ts2*(1.f/DMODEL) - mu*mu;
    float r = rsqrtf(var + LN_EPS);

    float4 o;
    float* po = &o.x;
    #pragma unroll
    for (int i=0;i<4;i++){
        int col = t4*4+i;
        po[i] = (a[i]-mu)*r*g[col] + bta[col];
    }
    *reinterpret_cast<float4*>(&out[base + t4*4]) = o;
}

// ---------------- host-side orchestration ----------------
static float* devPtr(float* symAddr){ return symAddr; }

extern "C" void kernel_launch(void* const* d_in, const int* in_sizes, int n_in,
                              void* d_out, int out_size)
{
    const float* x = (const float*)d_in[0];
    // per-direction parameter tables: [0]=forward (d_in[1..9]), [1]=backward (d_in[10..18])
    const float* in_w  [2] = {(const float*)d_in[1],  (const float*)d_in[10]};
    const float* conv_w[2] = {(const float*)d_in[2],  (const float*)d_in[11]};
    const float* conv_b[2] = {(const float*)d_in[3],  (const float*)d_in[12]};
    const float* xproj [2] = {(const float*)d_in[4],  (const float*)d_in[13]};
    const float* dt_w  [2] = {(const float*)d_in[5],  (const float*)d_in[14]};
    const float* dt_b  [2] = {(const float*)d_in[6],  (const float*)d_in[15]};
    const float* A_log [2] = {(const float*)d_in[7],  (const float*)d_in[16]};
    const float* Dp    [2] = {(const float*)d_in[8],  (const float*)d_in[17]};
    const float* out_w [2] = {(const float*)d_in[9],  (const float*)d_in[18]};
    const float* ln_f_g = (const float*)d_in[19];
    const float* ln_f_b = (const float*)d_in[20];
    const float* ln_b_g = (const float*)d_in[21];
    const float* ln_b_b = (const float*)d_in[22];
    const float* ln_ff_g= (const float*)d_in[23];
    const float* ln_ff_b= (const float*)d_in[24];
    const float* ffn_w1 = (const float*)d_in[25];
    const float* ffn_b1 = (const float*)d_in[26];
    const float* ffn_w2 = (const float*)d_in[27];
    const float* ffn_b2 = (const float*)d_in[28];
    float* outp = (float*)d_out;

    float *p_xz, *p_xc, *p_dbc, *p_dt, *p_yg, *p_mf, *p_mb, *p_h, *p_ff1, *p_ff2;
    float *p_hend, *p_P, *p_hin;
    cudaGetSymbolAddress((void**)&p_xz,  g_xz);
    cudaGetSymbolAddress((void**)&p_xc,  g_xc);
    cudaGetSymbolAddress((void**)&p_dbc, g_dbc);
    cudaGetSymbolAddress((void**)&p_dt,  g_dt);
    cudaGetSymbolAddress((void**)&p_yg,  g_yg);
    cudaGetSymbolAddress((void**)&p_mf,  g_mf);
    cudaGetSymbolAddress((void**)&p_mb,  g_mb);
    cudaGetSymbolAddress((void**)&p_h,   g_h);
    cudaGetSymbolAddress((void**)&p_ff1, g_ff1);
    cudaGetSymbolAddress((void**)&p_ff2, g_ff2);
    cudaGetSymbolAddress((void**)&p_hend,g_hend);
    cudaGetSymbolAddress((void**)&p_P,   g_P);
    cudaGetSymbolAddress((void**)&p_hin, g_hin);

    const int M = NTOK;

    for (int dir = 0; dir < 2; dir++) {
        // xz = x @ in_w^T   [M, 2048] K=512
        {
            dim3 grid(2*DI/128, M/128);
            sgemm_tn<128,128,8,8,8,0><<<grid,256>>>(x, DMODEL, in_w[dir], nullptr, p_xz, M, 2*DI, DMODEL);
        }
        // conv + silu
        conv_silu_kernel<<<(NTOK*DI)/256, 256>>>(p_xz, conv_w[dir], conv_b[dir], p_xc, dir);
        // dbc = xc @ xproj^T  [M, 64] K=1024
        {
            dim3 grid((DR+2*DS)/64, M/128);
            sgemm_tn<128,64,16,8,4,0><<<grid,256>>>(p_xc, DI, xproj[dir], nullptr, p_dbc, M, DR+2*DS, DI);
        }
        // dt = softplus(dbc[:, :32] @ dt_w^T + dt_b)  [M, 1024] K=32, lda=64
        {
            dim3 grid(DI/128, M/128);
            sgemm_tn<128,128,8,8,8,2><<<grid,256>>>(p_dbc, DR+2*DS, dt_w[dir], dt_b[dir], p_dt, M, DI, DR);
        }
        // chunked scan
        {
            dim3 grid1(DI/256, NCH, BSZ);
            scan_pass1<<<grid1,256>>>(p_dt, p_xc, p_dbc, A_log[dir], p_hend, p_P, dir);
            scan_pass2<<<(BSZ*DS*DI)/256,256>>>(p_hend, p_P, p_hin);
            scan_pass3<<<grid1,256>>>(p_dt, p_xc, p_dbc, A_log[dir], Dp[dir], p_xz, p_hin, p_yg, dir);
        }
        // mamba out = yg @ out_w^T  [M, 512] K=1024
        {
            dim3 grid(DMODEL/128, M/128);
            sgemm_tn<128,128,8,8,8,0><<<grid,256>>>(p_yg, DI, out_w[dir], nullptr,
                                                    dir ? p_mb : p_mf, M, DMODEL, DI);
        }
    }

    // h = 0.5*(LN(x+mf) + LN(x+mb))
    ln_combine_kernel<<<NTOK,128>>>(x, p_mf, p_mb, ln_f_g, ln_f_b, ln_b_g, ln_b_b, p_h);

    // ff1 = gelu(h @ w1^T + b1)  [M, 2048] K=512
    {
        dim3 grid(DFF/128, M/128);
        sgemm_tn<128,128,8,8,8,1><<<grid,256>>>(p_h, DMODEL, ffn_w1, ffn_b1, p_ff1, M, DFF, DMODEL);
    }
    // ff2 = ff1 @ w2^T + b2  [M, 512] K=2048
    {
        dim3 grid(DMODEL/128, M/128);
        sgemm_tn<128,128,8,8,8,0><<<grid,256>>>(p_ff1, DFF, ffn_w2, ffn_b2, p_ff2, M, DMODEL, DFF);
    }
    // out = LN(h + ff2)
    ln_final_kernel<<<NTOK,128>>>(p_h, p_ff2, ln_ff_g, ln_ff_b, outp);
}

// round 3
// speedup vs baseline: 2.5001x; 2.5001x over previous
#include <cuda_runtime.h>
#include <cuda_bf16.h>
#include <math.h>
#include <stdint.h>

// ---------------- problem constants ----------------
#define BSZ   8
#define SEQ   4096
#define DMODEL 512
#define DI    1024      // d_inner
#define DS    16        // d_state
#define DR    32        // dt_rank
#define DFF   2048
#define NTOK  (BSZ*SEQ) // 32768
#define NCH   32        // scan chunks
#define CS    128       // chunk size
#define LN_EPS 1e-5f

// ---------------- scratch (device globals) ----------------
__device__ float g_xz [(size_t)NTOK*2*DI];
__device__ float g_xc [(size_t)NTOK*DI];
__device__ float g_dbc[(size_t)NTOK*(DR+2*DS)];
__device__ float g_dt [(size_t)NTOK*DI];
__device__ float g_yg [(size_t)NTOK*DI];
__device__ float g_mf [(size_t)NTOK*DMODEL];
__device__ float g_mb [(size_t)NTOK*DMODEL];
__device__ float g_h  [(size_t)NTOK*DMODEL];
__device__ float g_ff1[(size_t)NTOK*DFF];
__device__ float g_ff2[(size_t)NTOK*DMODEL];
__device__ float g_hend[(size_t)BSZ*NCH*DS*DI];
__device__ float g_P   [(size_t)BSZ*NCH*DS*DI];
__device__ float g_hin [(size_t)BSZ*NCH*DS*DI];
__device__ float g_dtw2[(size_t)DI*64];   // zero-padded dt weights [DI,64]

// ---------------- math helpers ----------------
__device__ __forceinline__ float sigmoidf_(float x){ return 1.f/(1.f+__expf(-x)); }
__device__ __forceinline__ float geluf(float x){
    float x3 = x*x*x;
    return 0.5f*x*(1.f + tanhf(0.7978845608028654f*(x + 0.044715f*x3)));
}
__device__ __forceinline__ float softplusf(float x){
    return fmaxf(x,0.f) + log1pf(__expf(-fabsf(x)));
}
__device__ __forceinline__ float warpSum(float v){
    #pragma unroll
    for(int o=16;o;o>>=1) v += __shfl_xor_sync(0xffffffffu, v, o);
    return v;
}
__device__ __forceinline__ uint32_t smem_u32(const void* p){
    uint32_t a;
    asm("{ .reg .u64 t; cvta.to.shared.u64 t, %1; cvt.u32.u64 %0, t; }" : "=r"(a) : "l"(p));
    return a;
}

// ---------------- portable tensor-core primitives (sm_80+ PTX) ----------------
#define LDSM4(r, addr) \
    asm volatile("ldmatrix.sync.aligned.m8n8.x4.shared.b16 {%0,%1,%2,%3}, [%4];" \
        : "=r"((r)[0]), "=r"((r)[1]), "=r"((r)[2]), "=r"((r)[3]) : "r"(addr))

#define MMA16816(d, a, b0, b1) \
    asm volatile("mma.sync.aligned.m16n8k16.row.col.f32.bf16.bf16.f32 " \
        "{%0,%1,%2,%3}, {%4,%5,%6,%7}, {%8,%9}, {%0,%1,%2,%3};" \
        : "+f"((d)[0]), "+f"((d)[1]), "+f"((d)[2]), "+f"((d)[3]) \
        : "r"((a)[0]), "r"((a)[1]), "r"((a)[2]), "r"((a)[3]), "r"(b0), "r"(b1))

// fp32 -> (hi bf16 truncated, lo bf16 residual) split, 4 values at a time.
__device__ __forceinline__ void split_store(float4 v, char* hi, char* lo, uint32_t off){
    uint32_t bx = __float_as_uint(v.x), by = __float_as_uint(v.y);
    uint32_t bz = __float_as_uint(v.z), bw = __float_as_uint(v.w);
    uint32_t hxy = __byte_perm(bx, by, 0x7632);
    uint32_t hzw = __byte_perm(bz, bw, 0x7632);
    float lx = v.x - __uint_as_float(bx & 0xFFFF0000u);
    float ly = v.y - __uint_as_float(by & 0xFFFF0000u);
    float lz = v.z - __uint_as_float(bz & 0xFFFF0000u);
    float lw = v.w - __uint_as_float(bw & 0xFFFF0000u);
    __nv_bfloat162 l01 = __floats2bfloat162_rn(lx, ly);
    __nv_bfloat162 l23 = __floats2bfloat162_rn(lz, lw);
    *reinterpret_cast<uint2*>(hi + off) = make_uint2(hxy, hzw);
    *reinterpret_cast<uint2*>(lo + off) =
        make_uint2(*reinterpret_cast<uint32_t*>(&l01), *reinterpret_cast<uint32_t*>(&l23));
}
__device__ __forceinline__ uint32_t swzmask(int row){ return (uint32_t)(row & 7) << 4; }

// ============================================================================
// Tensor-core GEMM (mma.sync bf16, split-3 fp32-accurate):
//   C[M,N] = act(A[M,K](lda) @ B[N,K]^T + bias)
// CTA tile 128 x BN, K-chunks of 64, double-buffered SW128 SMEM.
// 8 warps in 2x4; warp tile 64 x (BN/4). ACT: 0=none, 1=gelu, 2=softplus
// ============================================================================
template<int BN, int ACT>
__global__ void __launch_bounds__(256, 1) gemm_mma(
    const float* __restrict__ A, int lda,
    const float* __restrict__ B,
    const float* __restrict__ bias,
    float* __restrict__ C, int ldc,
    int M, int N, int K)
{
    extern __shared__ char smem[];
    constexpr int NT    = BN/32;            // n-tiles (of 8) per warp
    constexpr int STAGE = 32768 + 2*BN*128; // Ah(16K)+Al(16K)+Bh+Bl
    constexpr int BREGS = BN/16;            // float4 per thread for B tile
    const int tid = threadIdx.x, lane = tid & 31, wid = tid >> 5;
    const int warpM = wid >> 2, warpN = wid & 3;
    const int m0 = blockIdx.y*128, n0 = blockIdx.x*BN;
    const uint32_t sb = smem_u32(smem);

    // ldmatrix lane-dependent address components (SW128, mask constant per lane)
    const int a_mrow = warpM*64 + (lane & 15);
    const uint32_t aRaw  = (uint32_t)a_mrow*128 + ((lane >> 4)*16);
    const uint32_t aMask = swzmask(a_mrow);
    const int b_nrow = warpN*(BN/4) + (lane & 7) + ((lane >> 4) & 1)*8;
    const uint32_t bRaw  = (uint32_t)b_nrow*128 + (((lane >> 3) & 1)*16);
    const uint32_t bMask = swzmask(b_nrow);

    float acc[4][NT][4];
    #pragma unroll
    for (int mt=0; mt<4; mt++)
        #pragma unroll
        for (int nt=0; nt<NT; nt++)
            #pragma unroll
            for (int q=0; q<4; q++) acc[mt][nt][q] = 0.f;

    const int NC = K/64;
    float4 regA[8], regB[BREGS];

    auto loadRegs = [&](int c){
        const float* Ab = A + (size_t)m0*lda + (size_t)c*64;
        #pragma unroll
        for (int i=0;i<8;i++){
            int idx = i*256 + tid; int row = idx >> 4, c4 = idx & 15;
            regA[i] = *reinterpret_cast<const float4*>(Ab + (size_t)row*lda + c4*4);
        }
        const float* Bb = B + (size_t)n0*K + (size_t)c*64;
        #pragma unroll
        for (int i=0;i<BREGS;i++){
            int idx = i*256 + tid; int row = idx >> 4, c4 = idx & 15;
            regB[i] = *reinterpret_cast<const float4*>(Bb + (size_t)row*K + c4*4);
        }
    };
    auto stsRegs = [&](int s){
        char* stg = smem + s*STAGE;
        #pragma unroll
        for (int i=0;i<8;i++){
            int idx = i*256 + tid; int row = idx >> 4, c4 = idx & 15;
            uint32_t off = (uint32_t)(row*128 + c4*8);
            off ^= ((off >> 3) & 0x70);
            split_store(regA[i], stg, stg + 16384, off);
        }
        #pragma unroll
        for (int i=0;i<BREGS;i++){
            int idx = i*256 + tid; int row = idx >> 4, c4 = idx & 15;
            uint32_t off = (uint32_t)(row*128 + c4*8);
            off ^= ((off >> 3) & 0x70);
            split_store(regB[i], stg + 32768, stg + 32768 + BN*128, off);
        }
    };

    loadRegs(0);
    stsRegs(0);
    __syncthreads();

    for (int c = 0; c < NC; c++){
        if (c+1 < NC) loadRegs(c+1);   // LDG latency overlaps the MMA block

        const uint32_t stg = sb + (c & 1)*STAGE;
        #pragma unroll
        for (int ks = 0; ks < 4; ks++){
            uint32_t ah[4][4], al[4][4];
            #pragma unroll
            for (int mt = 0; mt < 4; mt++){
                uint32_t off = (aRaw + mt*2048 + ks*32) ^ aMask;
                LDSM4(ah[mt], stg + off);
                LDSM4(al[mt], stg + 16384 + off);
            }
            uint32_t bh[NT][2], bl[NT][2];
            #pragma unroll
            for (int p = 0; p < NT/2; p++){
                uint32_t off = (bRaw + p*2048 + ks*32) ^ bMask;
                uint32_t r[4];
                LDSM4(r, stg + 32768 + off);
                bh[2*p][0]=r[0]; bh[2*p][1]=r[1]; bh[2*p+1][0]=r[2]; bh[2*p+1][1]=r[3];
                LDSM4(r, stg + 32768 + BN*128 + off);
                bl[2*p][0]=r[0]; bl[2*p][1]=r[1]; bl[2*p+1][0]=r[2]; bl[2*p+1][1]=r[3];
            }
            #pragma unroll
            for (int mt = 0; mt < 4; mt++)
                #pragma unroll
                for (int nt = 0; nt < NT; nt++){
                    MMA16816(acc[mt][nt], ah[mt], bh[nt][0], bh[nt][1]);
                    MMA16816(acc[mt][nt], al[mt], bh[nt][0], bh[nt][1]);
                    MMA16816(acc[mt][nt], ah[mt], bl[nt][0], bl[nt][1]);
                }
        }
        if (c+1 < NC) stsRegs((c+1) & 1);
        __syncthreads();
    }

    // ---- epilogue: regs -> GMEM (bias + activation) ----
    const int m_ep = m0 + warpM*64 + (lane >> 2);
    const int n_ep = n0 + warpN*(BN/4) + (lane & 3)*2;
    #pragma unroll
    for (int mt = 0; mt < 4; mt++){
        #pragma unroll
        for (int nt = 0; nt < NT; nt++){
            const int col = n_ep + nt*8;
            float b0 = bias ? bias[col]   : 0.f;
            float b1 = bias ? bias[col+1] : 0.f;
            float v0 = acc[mt][nt][0] + b0, v1 = acc[mt][nt][1] + b1;
            float v2 = acc[mt][nt][2] + b0, v3 = acc[mt][nt][3] + b1;
            if (ACT == 1){ v0=geluf(v0); v1=geluf(v1); v2=geluf(v2); v3=geluf(v3); }
            else if (ACT == 2){ v0=softplusf(v0); v1=softplusf(v1); v2=softplusf(v2); v3=softplusf(v3); }
            const int r0 = m_ep + mt*16;
            *reinterpret_cast<float2*>(&C[(size_t)r0*ldc + col])     = make_float2(v0, v1);
            *reinterpret_cast<float2*>(&C[(size_t)(r0+8)*ldc + col]) = make_float2(v2, v3);
        }
    }
}

// ---------------- zero-padded dt weight: [DI,64] = [dt_w | 0] ----------------
__global__ void pad_dtw_kernel(const float* __restrict__ dt_w, float* __restrict__ w2)
{
    int idx = blockIdx.x*blockDim.x + threadIdx.x;   // DI*64
    if (idx >= DI*64) return;
    int d = idx >> 6, c = idx & 63;
    w2[idx] = (c < DR) ? dt_w[d*DR + c] : 0.f;
}

// ---------------- depthwise conv (k=4) + bias + silu ----------------
__global__ void conv_silu_kernel(const float* __restrict__ xz,
                                 const float* __restrict__ w,
                                 const float* __restrict__ cb,
                                 float* __restrict__ xc, int dir)
{
    int idx = blockIdx.x*blockDim.x + threadIdx.x;
    if (idx >= NTOK*DI) return;
    int d = idx % DI;
    int t = (idx / DI) % SEQ;
    int b =  idx / (DI*SEQ);
    const float* base = xz + ((size_t)b*SEQ)*(2*DI) + d;
    float acc = cb[d];
    #pragma unroll
    for (int j=0;j<4;j++){
        int tt = (dir==0) ? (t-3+j) : (t+3-j);
        if (tt>=0 && tt<SEQ) acc = fmaf(w[d*4+j], base[(size_t)tt*(2*DI)], acc);
    }
    xc[idx] = acc * sigmoidf_(acc);
}

// ---------------- chunked selective scan ----------------
__global__ void scan_pass1(const float* __restrict__ dt,
                           const float* __restrict__ xc,
                           const float* __restrict__ dbc,
                           const float* __restrict__ A_log,
                           float* __restrict__ hend, float* __restrict__ Pout,
                           int dir)
{
    const int d = blockIdx.x*blockDim.x + threadIdx.x;
    const int c = blockIdx.y, b = blockIdx.z;
    __shared__ float sB[CS][DS];
    for (int i = threadIdx.x; i < CS*DS; i += blockDim.x) {
        int sl = i / DS, q = i % DS;
        int p  = dir ? (SEQ-1 - (c*CS+sl)) : (c*CS+sl);
        sB[sl][q] = dbc[((size_t)b*SEQ + p)*(DR+2*DS) + DR + q];
    }
    __syncthreads();

    float A[DS];
    #pragma unroll
    for (int n=0;n<DS;n++) A[n] = -__expf(A_log[d*DS + n]);

    float h[DS], P[DS];
    #pragma unroll
    for (int n=0;n<DS;n++){ h[n]=0.f; P[n]=1.f; }

    for (int s=0;s<CS;s++){
        int p = dir ? (SEQ-1 - (c*CS+s)) : (c*CS+s);
        size_t off = ((size_t)b*SEQ + p)*DI + d;
        float dtv = dt[off];
        float xv  = xc[off];
        float dtx = dtv*xv;
        #pragma unroll
        for (int n=0;n<DS;n++){
            float dA = __expf(dtv*A[n]);
            h[n] = fmaf(dA, h[n], dtx*sB[s][n]);
            P[n] *= dA;
        }
    }
    size_t base = (((size_t)b*NCH + c)*DS)*DI + d;
    #pragma unroll
    for (int n=0;n<DS;n++){ hend[base + (size_t)n*DI] = h[n]; Pout[base + (size_t)n*DI] = P[n]; }
}

__global__ void scan_pass2(const float* __restrict__ hend,
                           const float* __restrict__ P,
                           float* __restrict__ hin)
{
    int idx = blockIdx.x*blockDim.x + threadIdx.x;
    if (idx >= BSZ*DS*DI) return;
    int d = idx % DI;
    int n = (idx / DI) % DS;
    int b =  idx / (DI*DS);
    float h = 0.f;
    for (int c=0;c<NCH;c++){
        size_t off = (((size_t)b*NCH + c)*DS + n)*DI + d;
        hin[off] = h;
        h = fmaf(P[off], h, hend[off]);
    }
}

__global__ void scan_pass3(const float* __restrict__ dt,
                           const float* __restrict__ xc,
                           const float* __restrict__ dbc,
                           const float* __restrict__ A_log,
                           const float* __restrict__ Dp,
                           const float* __restrict__ xz,
                           const float* __restrict__ hin,
                           float* __restrict__ yg,
                           int dir)
{
    const int d = blockIdx.x*blockDim.x + threadIdx.x;
    const int c = blockIdx.y, b = blockIdx.z;
    __shared__ float sB[CS][DS];
    __shared__ float sC[CS][DS];
    for (int i = threadIdx.x; i < CS*2*DS; i += blockDim.x) {
        int sl = i / (2*DS), q = i % (2*DS);
        int p  = dir ? (SEQ-1 - (c*CS+sl)) : (c*CS+sl);
        float v = dbc[((size_t)b*SEQ + p)*(DR+2*DS) + DR + q];
        if (q < DS) sB[sl][q] = v; else sC[sl][q-DS] = v;
    }
    __syncthreads();

    float A[DS];
    #pragma unroll
    for (int n=0;n<DS;n++) A[n] = -__expf(A_log[d*DS + n]);
    float h[DS];
    {
        size_t base = (((size_t)b*NCH + c)*DS)*DI + d;
        #pragma unroll
        for (int n=0;n<DS;n++) h[n] = hin[base + (size_t)n*DI];
    }
    const float Dval = Dp[d];

    for (int s=0;s<CS;s++){
        int p = dir ? (SEQ-1 - (c*CS+s)) : (c*CS+s);
        size_t off = ((size_t)b*SEQ + p)*DI + d;
        float dtv = dt[off];
        float xv  = xc[off];
        float dtx = dtv*xv;
        float y = 0.f;
        #pragma unroll
        for (int n=0;n<DS;n++){
            float dA = __expf(dtv*A[n]);
            h[n] = fmaf(dA, h[n], dtx*sB[s][n]);
            y = fmaf(h[n], sC[s][n], y);
        }
        float zz = xz[((size_t)b*SEQ + p)*(2*DI) + DI + d];
        yg[off] = (y + xv*Dval) * (zz * sigmoidf_(zz));
    }
}

// ---------------- h = 0.5*(LN(x+mf; f) + LN(x+mb; b)) ----------------
__global__ void ln_combine_kernel(const float* __restrict__ x,
                                  const float* __restrict__ mf,
                                  const float* __restrict__ mb,
                                  const float* __restrict__ gf, const float* __restrict__ bf,
                                  const float* __restrict__ gb, const float* __restrict__ bb,
                                  float* __restrict__ hout)
{
    const int row = blockIdx.x;
    const size_t base = (size_t)row*DMODEL;
    const int t4 = threadIdx.x;
    float4 x4  = *reinterpret_cast<const float4*>(&x [base + t4*4]);
    float4 f4  = *reinterpret_cast<const float4*>(&mf[base + t4*4]);
    float4 b4  = *reinterpret_cast<const float4*>(&mb[base + t4*4]);
    float a[4] = {x4.x+f4.x, x4.y+f4.y, x4.z+f4.z, x4.w+f4.w};
    float c[4] = {x4.x+b4.x, x4.y+b4.y, x4.z+b4.z, x4.w+b4.w};
    float sa=0, sa2=0, sc=0, sc2=0;
    #pragma unroll
    for (int i=0;i<4;i++){ sa+=a[i]; sa2+=a[i]*a[i]; sc+=c[i]; sc2+=c[i]*c[i]; }

    __shared__ float red[4][4];
    float vals[4] = {sa, sa2, sc, sc2};
    int warp = threadIdx.x>>5, lane = threadIdx.x&31;
    #pragma unroll
    for (int q=0;q<4;q++){
        float w = warpSum(vals[q]);
        if (lane==0) red[q][warp] = w;
    }
    __syncthreads();
    float tot[4];
    #pragma unroll
    for (int q=0;q<4;q++) tot[q] = red[q][0]+red[q][1]+red[q][2]+red[q][3];

    float ma = tot[0]*(1.f/DMODEL);
    float va = tot[1]*(1.f/DMODEL) - ma*ma;
    float ra = rsqrtf(va + LN_EPS);
    float mc = tot[2]*(1.f/DMODEL);
    float vc = tot[3]*(1.f/DMODEL) - mc*mc;
    float rc = rsqrtf(vc + LN_EPS);

    float4 out;
    float* po = &out.x;
    #pragma unroll
    for (int i=0;i<4;i++){
        int col = t4*4+i;
        float la = (a[i]-ma)*ra*gf[col] + bf[col];
        float lc = (c[i]-mc)*rc*gb[col] + bb[col];
        po[i] = 0.5f*(la + lc);
    }
    *reinterpret_cast<float4*>(&hout[base + t4*4]) = out;
}

// ---------------- out = LN(h + ff2; ln_ff) ----------------
__global__ void ln_final_kernel(const float* __restrict__ h,
                                const float* __restrict__ ff2,
                                const float* __restrict__ g, const float* __restrict__ bta,
                                float* __restrict__ out)
{
    const int row = blockIdx.x;
    const size_t base = (size_t)row*DMODEL;
    const int t4 = threadIdx.x;
    float4 h4 = *reinterpret_cast<const float4*>(&h  [base + t4*4]);
    float4 f4 = *reinterpret_cast<const float4*>(&ff2[base + t4*4]);
    float a[4] = {h4.x+f4.x, h4.y+f4.y, h4.z+f4.z, h4.w+f4.w};
    float sa=0, sa2=0;
    #pragma unroll
    for (int i=0;i<4;i++){ sa+=a[i]; sa2+=a[i]*a[i]; }

    __shared__ float red[2][4];
    int warp = threadIdx.x>>5, lane = threadIdx.x&31;
    float w0 = warpSum(sa), w1 = warpSum(sa2);
    if (lane==0){ red[0][warp]=w0; red[1][warp]=w1; }
    __syncthreads();
    float ts  = red[0][0]+red[0][1]+red[0][2]+red[0][3];
    float ts2 = red[1][0]+red[1][1]+red[1][2]+red[1][3];
    float mu = ts*(1.f/DMODEL);
    float var = ts2*(1.f/DMODEL) - mu*mu;
    float r = rsqrtf(var + LN_EPS);

    float4 o;
    float* po = &o.x;
    #pragma unroll
    for (int i=0;i<4;i++){
        int col = t4*4+i;
        po[i] = (a[i]-mu)*r*g[col] + bta[col];
    }
    *reinterpret_cast<float4*>(&out[base + t4*4]) = o;
}

// ---------------- host orchestration ----------------
extern "C" void kernel_launch(void* const* d_in, const int* in_sizes, int n_in,
                              void* d_out, int out_size)
{
    const float* x = (const float*)d_in[0];
    const float* in_w  [2] = {(const float*)d_in[1],  (const float*)d_in[10]};
    const float* conv_w[2] = {(const float*)d_in[2],  (const float*)d_in[11]};
    const float* conv_b[2] = {(const float*)d_in[3],  (const float*)d_in[12]};
    const float* xproj [2] = {(const float*)d_in[4],  (const float*)d_in[13]};
    const float* dt_w  [2] = {(const float*)d_in[5],  (const float*)d_in[14]};
    const float* dt_b  [2] = {(const float*)d_in[6],  (const float*)d_in[15]};
    const float* A_log [2] = {(const float*)d_in[7],  (const float*)d_in[16]};
    const float* Dp    [2] = {(const float*)d_in[8],  (const float*)d_in[17]};
    const float* out_w [2] = {(const float*)d_in[9],  (const float*)d_in[18]};
    const float* ln_f_g = (const float*)d_in[19];
    const float* ln_f_b = (const float*)d_in[20];
    const float* ln_b_g = (const float*)d_in[21];
    const float* ln_b_b = (const float*)d_in[22];
    const float* ln_ff_g= (const float*)d_in[23];
    const float* ln_ff_b= (const float*)d_in[24];
    const float* ffn_w1 = (const float*)d_in[25];
    const float* ffn_b1 = (const float*)d_in[26];
    const float* ffn_w2 = (const float*)d_in[27];
    const float* ffn_b2 = (const float*)d_in[28];
    float* outp = (float*)d_out;

    float *p_xz, *p_xc, *p_dbc, *p_dt, *p_yg, *p_mf, *p_mb, *p_h, *p_ff1, *p_ff2;
    float *p_hend, *p_P, *p_hin, *p_dtw2;
    cudaGetSymbolAddress((void**)&p_xz,  g_xz);
    cudaGetSymbolAddress((void**)&p_xc,  g_xc);
    cudaGetSymbolAddress((void**)&p_dbc, g_dbc);
    cudaGetSymbolAddress((void**)&p_dt,  g_dt);
    cudaGetSymbolAddress((void**)&p_yg,  g_yg);
    cudaGetSymbolAddress((void**)&p_mf,  g_mf);
    cudaGetSymbolAddress((void**)&p_mb,  g_mb);
    cudaGetSymbolAddress((void**)&p_h,   g_h);
    cudaGetSymbolAddress((void**)&p_ff1, g_ff1);
    cudaGetSymbolAddress((void**)&p_ff2, g_ff2);
    cudaGetSymbolAddress((void**)&p_hend,g_hend);
    cudaGetSymbolAddress((void**)&p_P,   g_P);
    cudaGetSymbolAddress((void**)&p_hin, g_hin);
    cudaGetSymbolAddress((void**)&p_dtw2,g_dtw2);

    const int SM128 = 2*(32768 + 2*128*128);  // 131072
    const int SM64  = 2*(32768 + 2*64*128);   // 98304
    cudaFuncSetAttribute(gemm_mma<128,0>, cudaFuncAttributeMaxDynamicSharedMemorySize, SM128);
    cudaFuncSetAttribute(gemm_mma<128,1>, cudaFuncAttributeMaxDynamicSharedMemorySize, SM128);
    cudaFuncSetAttribute(gemm_mma<128,2>, cudaFuncAttributeMaxDynamicSharedMemorySize, SM128);
    cudaFuncSetAttribute(gemm_mma<64,0>,  cudaFuncAttributeMaxDynamicSharedMemorySize, SM64);

    const int M = NTOK;

    for (int dir = 0; dir < 2; dir++) {
        // xz = x @ in_w^T   [M, 2048] K=512
        gemm_mma<128,0><<<dim3(2*DI/128, M/128), 256, SM128>>>(
            x, DMODEL, in_w[dir], nullptr, p_xz, 2*DI, M, 2*DI, DMODEL);
        // conv + silu
        conv_silu_kernel<<<(NTOK*DI)/256, 256>>>(p_xz, conv_w[dir], conv_b[dir], p_xc, dir);
        // dbc = xc @ xproj^T  [M, 64] K=1024
        gemm_mma<64,0><<<dim3(1, M/128), 256, SM64>>>(
            p_xc, DI, xproj[dir], nullptr, p_dbc, DR+2*DS, M, DR+2*DS, DI);
        // dt = softplus(dbc @ [dt_w|0]^T + dt_b)  [M, 1024] K=64 (zero-padded cols kill B/C part)
        pad_dtw_kernel<<<(DI*64)/256, 256>>>(dt_w[dir], p_dtw2);
        gemm_mma<128,2><<<dim3(DI/128, M/128), 256, SM128>>>(
            p_dbc, DR+2*DS, p_dtw2, dt_b[dir], p_dt, DI, M, DI, 64);
        // chunked scan
        {
            dim3 grid1(DI/256, NCH, BSZ);
            scan_pass1<<<grid1,256>>>(p_dt, p_xc, p_dbc, A_log[dir], p_hend, p_P, dir);
            scan_pass2<<<(BSZ*DS*DI)/256,256>>>(p_hend, p_P, p_hin);
            scan_pass3<<<grid1,256>>>(p_dt, p_xc, p_dbc, A_log[dir], Dp[dir], p_xz, p_hin, p_yg, dir);
        }
        // mamba out = yg @ out_w^T  [M, 512] K=1024
        gemm_mma<128,0><<<dim3(DMODEL/128, M/128), 256, SM128>>>(
            p_yg, DI, out_w[dir], nullptr, dir ? p_mb : p_mf, DMODEL, M, DMODEL, DI);
    }

    // h = 0.5*(LN(x+mf) + LN(x+mb))
    ln_combine_kernel<<<NTOK,128>>>(x, p_mf, p_mb, ln_f_g, ln_f_b, ln_b_g, ln_b_b, p_h);

    // ff1 = gelu(h @ w1^T + b1)  [M, 2048] K=512
    gemm_mma<128,1><<<dim3(DFF/128, M/128), 256, SM128>>>(
        p_h, DMODEL, ffn_w1, ffn_b1, p_ff1, DFF, M, DFF, DMODEL);
    // ff2 = ff1 @ w2^T + b2  [M, 512] K=2048
    gemm_mma<128,0><<<dim3(DMODEL/128, M/128), 256, SM128>>>(
        p_ff1, DFF, ffn_w2, ffn_b2, p_ff2, DMODEL, M, DMODEL, DFF);
    // out = LN(h + ff2)
    ln_final_kernel<<<NTOK,128>>>(p_h, p_ff2, ln_ff_g, ln_ff_b, outp);
}